// round 1
// baseline (speedup 1.0000x reference)
#include <cuda_runtime.h>
#include <math.h>

// Problem: signal (32, 1024, 2) f32, interleaved channels.
// anded[t] = -|s| - log1p(exp(-2e5*|s|))/1e5   (exact stable minish over {s,-s})
// out[b,t] = suffix max over j>=t of anded[b,j] (EV_SCALE=1e9 maxish == hard max
//            to ~1e-9 abs, far below 1e-3 rel tolerance)
//
// One launch: grid (32 batches x 2 channels), 1024 threads/CTA.
// Reverse inclusive max-scan via Hillis-Steele in shared memory (10 steps).

static constexpr int T = 1024;
static constexpr int B = 32;

__global__ __launch_bounds__(1024)
void suffix_robustness_kernel(const float* __restrict__ signal,
                              float* __restrict__ out) {
    __shared__ float s[T];

    const int b  = blockIdx.x;   // batch 0..31
    const int ch = blockIdx.y;   // channel 0..1
    const int t  = threadIdx.x;  // time 0..1023

    // Load interleaved: signal[b, t, ch]
    float c = signal[(b * T + t) * 2 + ch];

    // anded = minish({c,-c}, 1e5) = -|c| - log1p(exp(-2e5*|c|))/1e5
    float a   = fabsf(c);
    float arg = -200000.0f * a;
    // expf underflows to 0 for arg < ~-87, log1pf(0)=0 -> exact -|c| branch-free
    float anded = -a - log1pf(expf(arg)) * 1e-5f;

    s[t] = anded;
    __syncthreads();

    // Reverse inclusive max-scan: s[t] = max(s[t..T-1])
    #pragma unroll
    for (int off = 1; off < T; off <<= 1) {
        float v = s[t];
        float w = (t + off < T) ? s[t + off] : -INFINITY;
        __syncthreads();
        s[t] = fmaxf(v, w);
        __syncthreads();
    }

    // Outputs: tuple (final, final_2) concatenated; each (32,1024) row-major.
    out[ch * (B * T) + b * T + t] = s[t];
}

extern "C" void kernel_launch(void* const* d_in, const int* in_sizes, int n_in,
                              void* d_out, int out_size) {
    const float* signal = (const float*)d_in[0];
    float* out = (float*)d_out;
    dim3 grid(B, 2);
    suffix_robustness_kernel<<<grid, T>>>(signal, out);
}

// round 2
// speedup vs baseline: 1.0979x; 1.0979x over previous
#include <cuda_runtime.h>
#include <math.h>

// signal (32, 1024, 2) f32 interleaved -> per (batch,channel):
//   anded[t] = -|s| - log1p(exp(-2e5|s|))/1e5
//   out[t]   = max_{j>=t} anded[j]   (suffix max; EV_SCALE=1e9 maxish == hard
//              max to ~1e-9 abs, far below 1e-3 tolerance)
//
// One launch, grid=32 (one CTA per batch), 1024 threads. Each thread loads one
// float2 (both channels of its timestep) and runs two interleaved suffix-max
// scans: 5x shfl_down per warp, ONE __syncthreads, then every warp redundantly
// scans the 32 warp totals from smem (no second barrier).

static constexpr int T = 1024;
static constexpr int B = 32;

__device__ __forceinline__ float anded_of(float c) {
    float a = fabsf(c);
    // expf underflows to 0 for a > ~4.4e-4 -> exact -|c|; branch-free & stable
    return -a - log1pf(expf(-200000.0f * a)) * 1e-5f;
}

__global__ __launch_bounds__(1024)
void suffix_robustness_kernel(const float2* __restrict__ signal,
                              float* __restrict__ out) {
    __shared__ float totx[32];
    __shared__ float toty[32];

    const int b    = blockIdx.x;
    const int t    = threadIdx.x;
    const int lane = t & 31;
    const int wid  = t >> 5;

    float2 s = signal[b * T + t];          // (ch0, ch1) at timestep t
    float vx = anded_of(s.x);
    float vy = anded_of(s.y);

    // Per-warp suffix-inclusive max: lane i -> max over lanes >= i.
    // shfl_down with lane+off >= 32 returns own value (identity for max).
    #pragma unroll
    for (int off = 1; off < 32; off <<= 1) {
        float ox = __shfl_down_sync(0xffffffffu, vx, off);
        float oy = __shfl_down_sync(0xffffffffu, vy, off);
        vx = fmaxf(vx, ox);
        vy = fmaxf(vy, oy);
    }

    // Lane 0 now holds the warp's total max; publish it.
    if (lane == 0) { totx[wid] = vx; toty[wid] = vy; }
    __syncthreads();

    // Every warp redundantly suffix-scans the 32 warp totals.
    float tx = totx[lane];
    float ty = toty[lane];
    #pragma unroll
    for (int off = 1; off < 32; off <<= 1) {
        float ox = __shfl_down_sync(0xffffffffu, tx, off);
        float oy = __shfl_down_sync(0xffffffffu, ty, off);
        tx = fmaxf(tx, ox);
        ty = fmaxf(ty, oy);
    }
    // Carry for this warp = max of totals of warps > wid = scanned value at
    // lane wid+1 (wid==31 has no successor -> -inf).
    float cx = __shfl_sync(0xffffffffu, tx, (wid + 1) & 31);
    float cy = __shfl_sync(0xffffffffu, ty, (wid + 1) & 31);
    if (wid == 31) { cx = -INFINITY; cy = -INFINITY; }

    float rx = fmaxf(vx, cx);
    float ry = fmaxf(vy, cy);

    // Tuple (final, final_2) concatenated, each (32,1024) row-major.
    out[b * T + t]           = rx;
    out[B * T + b * T + t]   = ry;
}

extern "C" void kernel_launch(void* const* d_in, const int* in_sizes, int n_in,
                              void* d_out, int out_size) {
    const float2* signal = (const float2*)d_in[0];
    float* out = (float*)d_out;
    suffix_robustness_kernel<<<B, T>>>(signal, out);
}